// round 10
// baseline (speedup 1.0000x reference)
#include <cuda_runtime.h>
#include <cuda_fp16.h>

#define TAB 2048
#define FULLMASK 0xffffffffu
typedef unsigned long long ull;

__device__ __half g_htabh[2][TAB * 128];   // fp16 length->h tables
__device__ float4 g_einv[1000000];         // per-edge SO3 invariants
__device__ float2 g_etf[1000000];          // per-edge (tf, bitcast ti)
__device__ float  g_wpk[2][2][4096];       // [filt][hi/lo][ks*1024 + n*8 + tk*2 + p]

__device__ __forceinline__ float silu_f(float x) {
    float h = 0.5f * x, t;
    asm("tanh.approx.f32 %0, %1;" : "=f"(t) : "f"(h));
    return fmaf(h, t, h);
}
__device__ __forceinline__ float silu_acc(float x) { return __fdividef(x, 1.0f + __expf(-x)); }

__device__ __forceinline__ ull dup2(float x) {
    ull r; unsigned u = __float_as_uint(x);
    asm("mov.b64 %0, {%1,%1};" : "=l"(r) : "r"(u)); return r;
}
__device__ __forceinline__ void fma2(ull &d, ull a, ull b) {
    asm("fma.rn.f32x2 %0, %1, %2, %0;" : "+l"(d) : "l"(a), "l"(b));
}
__device__ __forceinline__ void unpack2(ull v, float &lo, float &hi) {
    unsigned a, b; asm("mov.b64 {%0,%1}, %2;" : "=r"(a), "=r"(b) : "l"(v));
    lo = __uint_as_float(a); hi = __uint_as_float(b);
}
__device__ __forceinline__ unsigned tf32_rna(float x) {
    unsigned r; asm("cvt.rna.tf32.f32 %0, %1;" : "=r"(r) : "f"(x)); return r;
}
__device__ __forceinline__ void mma_tf32(float c[4],
    unsigned a0, unsigned a1, unsigned a2, unsigned a3, unsigned b0, unsigned b1)
{
    asm volatile(
        "mma.sync.aligned.m16n8k8.row.col.f32.tf32.tf32.f32 "
        "{%0,%1,%2,%3}, {%4,%5,%6,%7}, {%8,%9}, {%0,%1,%2,%3};"
        : "+f"(c[0]), "+f"(c[1]), "+f"(c[2]), "+f"(c[3])
        : "r"(a0), "r"(a1), "r"(a2), "r"(a3), "r"(b0), "r"(b1));
}

// ===========================================================================
// Fused setup kernel. Grid sections (concurrent):
//   [0,16)        : pack layer-2 edge weights into hi/lo tf32 MMA layout
//   [16,144)      : build fp16 length->h tables
//   [144,144+PB)  : per-edge invariants + table index
//   [144+PB, ...) : node update
// ===========================================================================
__global__ void __launch_bounds__(256) setup_kernel(
    const float* __restrict__ invf, const float* __restrict__ evf,
    const int* __restrict__ senders, const int* __restrict__ receivers,
    const float* __restrict__ lengths,
    const float* __restrict__ fi_rbf_w1, const float* __restrict__ fi_rbf_b1,
    const float* __restrict__ fi_rbf_w2, const float* __restrict__ fi_rbf_b2,
    const float* __restrict__ fe_rbf_w1, const float* __restrict__ fe_rbf_b1,
    const float* __restrict__ fe_rbf_w2, const float* __restrict__ fe_rbf_b2,
    const float* __restrict__ fi_ev_w2, const float* __restrict__ fe_ev_w2,
    const float* __restrict__ w_int, const float* __restrict__ b_int,
    float* __restrict__ out1, float* __restrict__ out2,
    int N, int E, int PB)
{
    int bid = blockIdx.x;
    int tid = threadIdx.x;

    if (bid < 16) {
        // -------- pack edge layer-2 weights: hi/lo tf32 split, MMA B layout --
        int g = bid * 256 + tid;            // 4096 = 2 filt * 2048
        int filt = g >> 11;
        int j = g & 2047;
        int ks = j >> 9;                    // 0..3
        int rem = j & 511;
        int n = rem >> 2;                   // 0..127
        int tk = rem & 3;                   // 0..3
        const float* w2 = filt ? fe_ev_w2 : fi_ev_w2;
        int k0 = ks * 8 + tk;
        float wa = __ldg(&w2[k0 * 128 + n]);
        float wb = __ldg(&w2[(k0 + 4) * 128 + n]);
        float ha = __uint_as_float(tf32_rna(wa));
        float hb = __uint_as_float(tf32_rna(wb));
        int idx = ks * 1024 + n * 8 + tk * 2;
        g_wpk[filt][0][idx]     = ha;
        g_wpk[filt][0][idx + 1] = hb;
        g_wpk[filt][1][idx]     = __uint_as_float(tf32_rna(wa - ha));
        g_wpk[filt][1][idx + 1] = __uint_as_float(tf32_rna(wb - hb));
        return;
    }

    if (bid < 144) {
        // -------- table build: 64 blocks per filter, 32 rows/block ----------
        int tb = bid - 16;
        int filt = tb >> 6;
        const float* w1 = filt ? fe_rbf_w1 : fi_rbf_w1;
        const float* b1 = filt ? fe_rbf_b1 : fi_rbf_b1;
        const float* w2 = filt ? fe_rbf_w2 : fi_rbf_w2;
        const float* b2 = filt ? fe_rbf_b2 : fi_rbf_b2;
        __shared__ float h1s[128];
        int f = tid & 127;
        float w1col[32];
#pragma unroll
        for (int k = 0; k < 32; k++) w1col[k] = __ldg(&w1[k * 128 + f]);
        float b1f = __ldg(&b1[f]), b2f = __ldg(&b2[f]);
        const float step  = 5.0f / 31.0f;
        const float gamma = 0.5f / (step * step);
        const float dx    = 5.0f / (float)(TAB - 1);
        int r0 = (tb & 63) * 32;
        for (int rr = 0; rr < 32; rr++) {
            int row = r0 + rr;
            float x = (float)row * dx;
            float a1 = b1f;
#pragma unroll
            for (int k = 0; k < 32; k++) {
                float d = x - (float)k * step;
                a1 = fmaf(__expf(-gamma * d * d), w1col[k], a1);
            }
            h1s[f] = silu_acc(a1);
            __syncthreads();
            float a2 = b2f;
#pragma unroll 16
            for (int k = 0; k < 128; k++) a2 = fmaf(h1s[k], __ldg(&w2[k * 128 + f]), a2);
            g_htabh[filt][(size_t)row * 128 + f] = __float2half_rn(silu_acc(a2));
            __syncthreads();
        }
        return;
    }

    if (bid < 144 + PB) {
        // -------- edge prep ------------------------------------------------
        int e = (bid - 144) * 256 + tid;
        if (e >= E) return;
        const float tscale = (float)(TAB - 1) / 5.0f;
        int sN = __ldg(senders + e), rN = __ldg(receivers + e);
        const float4* As = reinterpret_cast<const float4*>(evf) + (size_t)sN * 4;
        const float4* Ar = reinterpret_cast<const float4*>(evf) + (size_t)rN * 4;
        float4 a, b; float dx, dy, dz, dw;
        float i0, i1, i2, i3;
        a = __ldg(As);     b = __ldg(Ar);     dx = a.x-b.x; dy = a.y-b.y; dz = a.z-b.z; dw = a.w-b.w;
        i0 = dx*dx; i1 = dy*dy + dz*dz + dw*dw;
        a = __ldg(As + 1); b = __ldg(Ar + 1); dx = a.x-b.x; dy = a.y-b.y; dz = a.z-b.z; dw = a.w-b.w;
        i2 = dx*dx + dy*dy + dz*dz + dw*dw;
        a = __ldg(As + 2); b = __ldg(Ar + 2); dx = a.x-b.x; dy = a.y-b.y; dz = a.z-b.z; dw = a.w-b.w;
        i2 += dx*dx; i3 = dy*dy + dz*dz + dw*dw;
        a = __ldg(As + 3); b = __ldg(Ar + 3); dx = a.x-b.x; dy = a.y-b.y; dz = a.z-b.z; dw = a.w-b.w;
        i3 += dx*dx + dy*dy + dz*dz + dw*dw;
        float xf = __ldg(lengths + e) * tscale;
        int ti = (int)xf;
        if (ti < 0) ti = 0; if (ti > TAB - 2) ti = TAB - 2;
        g_einv[e] = make_float4(i0, i1, i2, i3);
        g_etf[e]  = make_float2(xf - (float)ti, __int_as_float(ti));
        return;
    }

    // -------- node update: 8 nodes per warp, f32x2 pairs ---------------------
    __shared__ float2 xs[8][4][136];
    int warp = tid >> 5, lane = tid & 31;
    int ngrp = (N + 7) >> 3;
    int grp = (bid - 144 - PB) * 8 + warp;
    if (grp >= ngrp) return;
    int nbase = grp * 8;
    int o4 = (lane < 4) ? (128 + lane) : lane;

    float attv[8];
#pragma unroll
    for (int nd = 0; nd < 8; nd++) {
        int n = nbase + nd; if (n >= N) n = N - 1;
        float* Xp = reinterpret_cast<float*>(xs[warp][nd >> 1]) + (nd & 1);
#pragma unroll
        for (int j = 0; j < 4; j++)
            Xp[2 * (lane + 32 * j)] = 2.0f * __ldg(invf + (size_t)n * 128 + lane + 32 * j);
        float av = 0.f, dsq = 0.f;
        if (lane < 16) { av = 2.0f * __ldg(evf + (size_t)n * 16 + lane); dsq = av * av; }
        attv[nd] = av;
        float v0 = __shfl_sync(FULLMASK, dsq, 0);
        float v1 = __shfl_sync(FULLMASK, dsq, 1) + __shfl_sync(FULLMASK, dsq, 2)
                 + __shfl_sync(FULLMASK, dsq, 3);
        float v2 = __shfl_sync(FULLMASK, dsq, 4) + __shfl_sync(FULLMASK, dsq, 5)
                 + __shfl_sync(FULLMASK, dsq, 6) + __shfl_sync(FULLMASK, dsq, 7)
                 + __shfl_sync(FULLMASK, dsq, 8);
        float v3 = __shfl_sync(FULLMASK, dsq, 9) + __shfl_sync(FULLMASK, dsq, 10)
                 + __shfl_sync(FULLMASK, dsq, 11) + __shfl_sync(FULLMASK, dsq, 12)
                 + __shfl_sync(FULLMASK, dsq, 13) + __shfl_sync(FULLMASK, dsq, 14)
                 + __shfl_sync(FULLMASK, dsq, 15);
        if (lane == 0) { Xp[2*128] = v0; Xp[2*129] = v1; Xp[2*130] = v2; Xp[2*131] = v3; }
    }
    __syncwarp();

    ull acc[4][5];
    {
        ull d0 = dup2(__ldg(b_int + lane)),      d1 = dup2(__ldg(b_int + 32 + lane));
        ull d2 = dup2(__ldg(b_int + 64 + lane)), d3 = dup2(__ldg(b_int + 96 + lane));
        ull d4 = dup2(__ldg(b_int + o4));
#pragma unroll
        for (int p = 0; p < 4; p++) {
            acc[p][0] = d0; acc[p][1] = d1; acc[p][2] = d2; acc[p][3] = d3; acc[p][4] = d4;
        }
    }
#pragma unroll 2
    for (int i = 0; i < 132; i++) {
        const float* wr = w_int + i * 132;
        ull w0 = dup2(__ldg(wr + lane)),      w1 = dup2(__ldg(wr + 32 + lane));
        ull w2 = dup2(__ldg(wr + 64 + lane)), w3 = dup2(__ldg(wr + 96 + lane));
        ull w4 = dup2(__ldg(wr + o4));
#pragma unroll
        for (int p = 0; p < 4; p++) {
            ull x = reinterpret_cast<const ull*>(xs[warp][p])[i];
            fma2(acc[p][0], w0, x); fma2(acc[p][1], w1, x);
            fma2(acc[p][2], w2, x); fma2(acc[p][3], w3, x);
            fma2(acc[p][4], w4, x);
        }
    }
#pragma unroll
    for (int nd = 0; nd < 8; nd++) {
        int n = nbase + nd;
        if (n >= N) break;
        int p = nd >> 1, s = nd & 1;
        const float* Xp = reinterpret_cast<const float*>(xs[warp][p]) + s;
        float lo, hi, a0, a1, a2, a3, a4;
        unpack2(acc[p][0], lo, hi); a0 = s ? hi : lo;
        unpack2(acc[p][1], lo, hi); a1 = s ? hi : lo;
        unpack2(acc[p][2], lo, hi); a2 = s ? hi : lo;
        unpack2(acc[p][3], lo, hi); a3 = s ? hi : lo;
        unpack2(acc[p][4], lo, hi); a4 = s ? hi : lo;
        out1[(size_t)n * 128 + lane]      = Xp[2 * (lane)]      + a0;
        out1[(size_t)n * 128 + 32 + lane] = Xp[2 * (32 + lane)] + a1;
        out1[(size_t)n * 128 + 64 + lane] = Xp[2 * (64 + lane)] + a2;
        out1[(size_t)n * 128 + 96 + lane] = Xp[2 * (96 + lane)] + a3;
        float c0 = __shfl_sync(FULLMASK, a4, 0), c1 = __shfl_sync(FULLMASK, a4, 1);
        float c2 = __shfl_sync(FULLMASK, a4, 2), c3 = __shfl_sync(FULLMASK, a4, 3);
        if (lane < 16) {
            float bs = (lane == 0) ? c0 : ((lane < 4) ? c1 : ((lane < 9) ? c2 : c3));
            out2[(size_t)n * 16 + lane] = attv[nd] * (1.0f + bs);
        }
    }
}

// ===========================================================================
// Edge kernel: tf32 tensor-core layer 2 with hi/lo compensation (3 MMAs).
// Warp = 16 edges x 128 feats. blockIdx.y = filter.
// ===========================================================================
__global__ void __launch_bounds__(128, 4) edge_kernel(
    const float* __restrict__ fi_w1, const float* __restrict__ fi_b1,
    const float* __restrict__ fi_b2,
    const float* __restrict__ fe_w1, const float* __restrict__ fe_b1,
    const float* __restrict__ fe_b2,
    float* __restrict__ fwi, float* __restrict__ fwe, int E)
{
    int filt = blockIdx.y;
    const float* we1 = filt ? fe_w1 : fi_w1;
    const float* be1 = filt ? fe_b1 : fi_b1;
    const float* be2 = filt ? fe_b2 : fi_b2;
    float* outp = filt ? fwe : fwi;
    const __half* tab = g_htabh[filt];

    __shared__ __align__(16) float s_w[2][4096];     // hi/lo packed weights (32 KB)
    __shared__ __align__(16) float s_e1[4][32][24];  // [warp][k][edge] stride 24
    __shared__ __align__(16) float4 s_inv[4][16];
    __shared__ float s_tf[4][16];
    __shared__ int   s_ti[4][16];
    __shared__ __align__(8) float s_bias[128];

    int tid = threadIdx.x;
    {
        const float* src = g_wpk[filt][0];
        for (int i = tid; i < 8192; i += 128)
            (&s_w[0][0])[i] = src[i];
        if (tid < 128) s_bias[tid] = __ldg(be2 + tid);
    }
    __syncthreads();

    int warp = tid >> 5, lane = tid & 31;
    int tg = lane >> 2;     // groupID: edge row 0..7
    int tq = lane & 3;      // thread-in-group
    // layer-1 weights: lane = hidden k
    float w1l0 = __ldg(we1 + lane),      w1l1 = __ldg(we1 + 32 + lane);
    float w1l2 = __ldg(we1 + 64 + lane), w1l3 = __ldg(we1 + 96 + lane);
    float bl   = __ldg(be1 + lane);

    int gw = blockIdx.x * 4 + warp;
    int nwarps = gridDim.x * 4;

    for (int base = gw * 16; base < E; base += nwarps * 16) {
        // ---- stage 16 edges ----
        if (lane < 16) {
            int e = base + lane; if (e >= E) e = E - 1;
            s_inv[warp][lane] = g_einv[e];
            float2 m = g_etf[e];
            s_tf[warp][lane] = m.x;
            s_ti[warp][lane] = __float_as_int(m.y);
        }
        __syncwarp();

        // ---- layer 1: lane = k, 16 edges ----
        {
            float acc[16];
#pragma unroll
            for (int e = 0; e < 16; e++) {
                float4 v = s_inv[warp][e];
                acc[e] = silu_f(fmaf(v.x, w1l0, fmaf(v.y, w1l1,
                                fmaf(v.z, w1l2, fmaf(v.w, w1l3, bl)))));
            }
            float4* dst = reinterpret_cast<float4*>(&s_e1[warp][lane][0]);
            dst[0] = make_float4(acc[0], acc[1], acc[2], acc[3]);
            dst[1] = make_float4(acc[4], acc[5], acc[6], acc[7]);
            dst[2] = make_float4(acc[8], acc[9], acc[10], acc[11]);
            dst[3] = make_float4(acc[12], acc[13], acc[14], acc[15]);
        }
        __syncwarp();

        // ---- layer 2: tf32 MMA, C[16 n-tiles][4] ----
        float c[16][4];
#pragma unroll
        for (int nt = 0; nt < 16; nt++) {
            float2 bv = *reinterpret_cast<const float2*>(&s_bias[nt * 8 + tq * 2]);
            c[nt][0] = bv.x; c[nt][1] = bv.y; c[nt][2] = bv.x; c[nt][3] = bv.y;
        }
#pragma unroll
        for (int ks = 0; ks < 4; ks++) {
            // A frags: A[edge][k], a0=(tg,k0+tq) a1=(tg+8,k0+tq) a2=(tg,k0+tq+4) a3=(tg+8,k0+tq+4)
            float f0 = s_e1[warp][ks * 8 + tq][tg];
            float f1 = s_e1[warp][ks * 8 + tq][tg + 8];
            float f2 = s_e1[warp][ks * 8 + tq + 4][tg];
            float f3 = s_e1[warp][ks * 8 + tq + 4][tg + 8];
            unsigned ah0 = tf32_rna(f0), ah1 = tf32_rna(f1);
            unsigned ah2 = tf32_rna(f2), ah3 = tf32_rna(f3);
            unsigned al0 = tf32_rna(f0 - __uint_as_float(ah0));
            unsigned al1 = tf32_rna(f1 - __uint_as_float(ah1));
            unsigned al2 = tf32_rna(f2 - __uint_as_float(ah2));
            unsigned al3 = tf32_rna(f3 - __uint_as_float(ah3));
            const float2* whb = reinterpret_cast<const float2*>(&s_w[0][ks * 1024]);
            const float2* wlb = reinterpret_cast<const float2*>(&s_w[1][ks * 1024]);
#pragma unroll
            for (int nt = 0; nt < 16; nt++) {
                int off = (nt * 8 + tg) * 4 + tq;
                float2 bh = whb[off];
                float2 bo = wlb[off];
                unsigned bh0 = __float_as_uint(bh.x), bh1 = __float_as_uint(bh.y);
                unsigned bl0 = __float_as_uint(bo.x), bl1 = __float_as_uint(bo.y);
                mma_tf32(c[nt], ah0, ah1, ah2, ah3, bh0, bh1);
                mma_tf32(c[nt], al0, al1, al2, al3, bh0, bh1);
                mma_tf32(c[nt], ah0, ah1, ah2, ah3, bl0, bl1);
            }
        }

        // ---- epilogue: silu + fp16 table lerp + store ----
#pragma unroll
        for (int hh = 0; hh < 2; hh++) {
            int r = tg + hh * 8;
            int e = base + r;
            float tf = s_tf[warp][r];
            int   ti = s_ti[warp][r];
            if (e < E) {
                const __half2* t0 = reinterpret_cast<const __half2*>(tab) + (size_t)ti * 64;
#pragma unroll
                for (int nt = 0; nt < 16; nt++) {
                    int h2i = nt * 4 + tq;          // feat pair index (f0>>1)
                    __half2 ha = __ldg(t0 + h2i);
                    __half2 hb = __ldg(t0 + 64 + h2i);
                    float2 fa = __half22float2(ha);
                    float2 fb = __half22float2(hb);
                    float cx = c[nt][hh * 2], cy = c[nt][hh * 2 + 1];
                    float2 o;
                    o.x = fmaf(tf, fb.x - fa.x, fa.x) + silu_f(cx);
                    o.y = fmaf(tf, fb.y - fa.y, fa.y) + silu_f(cy);
                    *reinterpret_cast<float2*>(outp + (size_t)e * 128 + nt * 8 + tq * 2) = o;
                }
            }
        }
        __syncwarp();
    }
}

// ---------------------------------------------------------------------------
extern "C" void kernel_launch(void* const* d_in, const int* in_sizes, int n_in,
                              void* d_out, int out_size)
{
    const float* invf      = (const float*)d_in[0];
    const float* evf       = (const float*)d_in[1];
    const int*   senders   = (const int*)  d_in[2];
    const int*   receivers = (const int*)  d_in[3];
    const float* lengths   = (const float*)d_in[5];
    const float* fi_rbf_w1 = (const float*)d_in[7];
    const float* fi_rbf_b1 = (const float*)d_in[8];
    const float* fi_rbf_w2 = (const float*)d_in[9];
    const float* fi_rbf_b2 = (const float*)d_in[10];
    const float* fi_ev_w1  = (const float*)d_in[11];
    const float* fi_ev_b1  = (const float*)d_in[12];
    const float* fi_ev_w2  = (const float*)d_in[13];
    const float* fi_ev_b2  = (const float*)d_in[14];
    const float* fe_rbf_w1 = (const float*)d_in[15];
    const float* fe_rbf_b1 = (const float*)d_in[16];
    const float* fe_rbf_w2 = (const float*)d_in[17];
    const float* fe_rbf_b2 = (const float*)d_in[18];
    const float* fe_ev_w1  = (const float*)d_in[19];
    const float* fe_ev_b1  = (const float*)d_in[20];
    const float* fe_ev_w2  = (const float*)d_in[21];
    const float* fe_ev_b2  = (const float*)d_in[22];
    const float* w_int     = (const float*)d_in[23];
    const float* b_int     = (const float*)d_in[24];

    int N = in_sizes[0] / 128;
    int E = in_sizes[5];

    float* out1 = (float*)d_out;
    float* out2 = out1 + (size_t)N * 128;
    float* fwi  = out2 + (size_t)N * 16;
    float* fwe  = fwi  + (size_t)E * 128;

    int PB = (E + 255) / 256;
    int NB = (((N + 7) / 8) + 7) / 8;

    setup_kernel<<<144 + PB + NB, 256>>>(
        invf, evf, senders, receivers, lengths,
        fi_rbf_w1, fi_rbf_b1, fi_rbf_w2, fi_rbf_b2,
        fe_rbf_w1, fe_rbf_b1, fe_rbf_w2, fe_rbf_b2,
        fi_ev_w2, fe_ev_w2,
        w_int, b_int, out1, out2, N, E, PB);

    edge_kernel<<<dim3(296, 2), 128>>>(
        fi_ev_w1, fi_ev_b1, fi_ev_b2,
        fe_ev_w1, fe_ev_b1, fe_ev_b2,
        fwi, fwe, E);
}